// round 14
// baseline (speedup 1.0000x reference)
#include <cuda_runtime.h>
#include <cuda_bf16.h>
#include <cstdint>
#include <cstddef>

#define VOCAB   50000
#define EMB     256
#define HID     512
#define NBATCH  256
#define T       512
#define NB      512
#define NBLOCKS 128
#define THREADS 512

// ---- recurrent kernel SMEM ----
#define R_BHI   0           // 64 rows x 1024 B (Whh hi, swizzled)      64 KB
#define R_BLO   65536       // 64 KB
#define R_A     131072      // 2 bufs x 32 KB (hi 16K + lo 16K)         64 KB
#define R_SMEM  196608

// ---- phase A kernel SMEM ----
#define P_BHI   0           // 64 rows x 512 B (Wih hi)                 32 KB
#define P_BLO   32768
#define P_A     65536       // 2 bufs x 32 KB
#define P_TOK   131072      // 128 ints
#define P_SMEM  131584

__device__ __nv_bfloat16 g_ehi[(size_t)VOCAB * EMB];
__device__ __nv_bfloat16 g_elo[(size_t)VOCAB * EMB];
__device__ __nv_bfloat16 g_hhi[2][NB * HID];
__device__ __nv_bfloat16 g_hlo[2][NB * HID];
// XG in fragment-native tiles: tile id = ((t%256)*32 + hg)*4 + bg, 8192 floats each
// thread offset tid*16. g_xgA: t in [0,256), g_xgB: t in [256,512). t-stride = 2^20 floats.
__device__ float g_xgA[268435456];
__device__ float g_xgB[268435456];
__device__ unsigned g_cnt, g_gen;

// ---------------- helpers ----------------
__device__ __forceinline__ uint32_t smem_u32(const void* p) {
    uint32_t a;
    asm("{ .reg .u64 t; cvta.to.shared.u64 t, %1; cvt.u32.u64 %0, t; }" : "=r"(a) : "l"(p));
    return a;
}
__device__ __forceinline__ void cp16_ca(uint32_t d, const void* s) {
    asm volatile("cp.async.ca.shared.global [%0], [%1], 16;" :: "r"(d), "l"(s));
}
__device__ __forceinline__ void cp16_cg(uint32_t d, const void* s) {
    asm volatile("cp.async.cg.shared.global [%0], [%1], 16;" :: "r"(d), "l"(s));
}
__device__ __forceinline__ void ldsm4(uint32_t& r0, uint32_t& r1, uint32_t& r2, uint32_t& r3,
                                      uint32_t addr) {
    asm volatile("ldmatrix.sync.aligned.m8n8.x4.shared.b16 {%0,%1,%2,%3}, [%4];"
                 : "=r"(r0), "=r"(r1), "=r"(r2), "=r"(r3) : "r"(addr));
}
__device__ __forceinline__ void mma16816(float* c, const uint32_t* a, const uint32_t* b) {
    asm volatile(
        "mma.sync.aligned.m16n8k16.row.col.f32.bf16.bf16.f32 "
        "{%0,%1,%2,%3},{%4,%5,%6,%7},{%8,%9},{%0,%1,%2,%3};"
        : "+f"(c[0]), "+f"(c[1]), "+f"(c[2]), "+f"(c[3])
        : "r"(a[0]), "r"(a[1]), "r"(a[2]), "r"(a[3]), "r"(b[0]), "r"(b[1]));
}
__device__ __forceinline__ float sigf(float x) {
    return __fdividef(1.0f, 1.0f + __expf(-x));
}
__device__ __forceinline__ float tanhx(float x) {
    return __fmaf_rn(2.0f, sigf(2.0f * x), -1.0f);
}
__device__ __forceinline__ void grid_sync() {
    __syncthreads();
    if (threadIdx.x == 0) {
        volatile unsigned* genp = &g_gen;
        unsigned g = *genp;
        __threadfence();
        if (atomicAdd(&g_cnt, 1u) == NBLOCKS - 1) {
            g_cnt = 0;
            __threadfence();
            *genp = g + 1;
        } else {
            while (*genp == g) { }
        }
    }
    __syncthreads();
}

// Shared k64-chunk MMA
__device__ __forceinline__ void chunk_compute(
    uint32_t aBuf, uint32_t a_off,
    uint32_t bHi0, uint32_t bHi1, uint32_t bLo0, uint32_t bLo1,
    uint32_t nx7, uint32_t kbit, int kc0, float acc[4][4])
{
#pragma unroll
    for (int s = 0; s < 4; s++) {
        uint32_t ah[4], al[4];
        ldsm4(ah[0], ah[1], ah[2], ah[3], aBuf + s * 4096 + a_off);
        ldsm4(al[0], al[1], al[2], al[3], aBuf + 16384 + s * 4096 + a_off);
        const uint32_t kc = (uint32_t)(kc0 + s * 2) + kbit;
        const uint32_t o = ((kc ^ nx7) << 4);
        uint32_t bh[4][2], bl[4][2];
        ldsm4(bh[0][0], bh[0][1], bh[1][0], bh[1][1], bHi0 + o);
        ldsm4(bh[2][0], bh[2][1], bh[3][0], bh[3][1], bHi1 + o);
        ldsm4(bl[0][0], bl[0][1], bl[1][0], bl[1][1], bLo0 + o);
        ldsm4(bl[2][0], bl[2][1], bl[3][0], bl[3][1], bLo1 + o);
#pragma unroll
        for (int ni = 0; ni < 4; ni++) {
            mma16816(acc[ni], ah, bh[ni]);
            mma16816(acc[ni], ah, bl[ni]);
            mma16816(acc[ni], al, bh[ni]);
        }
    }
}

// ---------------- prep ----------------
__global__ void prep_kernel(const float* __restrict__ emb) {
    const size_t stride = (size_t)gridDim.x * blockDim.x;
    size_t i = (size_t)blockIdx.x * blockDim.x + threadIdx.x;
    const size_t total = (size_t)VOCAB * EMB;
    for (size_t p = i; p < total; p += stride) {
        float v = emb[p];
        __nv_bfloat16 h = __float2bfloat16(v);
        g_ehi[p] = h;
        g_elo[p] = __float2bfloat16(v - __bfloat162float(h));
    }
    const __nv_bfloat16 z = __float2bfloat16(0.0f);
    for (size_t p = i; p < (size_t)NB * HID; p += stride) {
        g_hhi[0][p] = z;
        g_hlo[0][p] = z;
    }
}

// ---------------- Phase A: XG tiles = Wih . emb(tok) + bias ----------------
__global__ void __launch_bounds__(THREADS, 1)
xg_kernel(const int* __restrict__ in1, const int* __restrict__ in2,
          const float* __restrict__ Wih,
          const float* __restrict__ bih, const float* __restrict__ bhh)
{
    extern __shared__ char smem[];
    const uint32_t sb = smem_u32(smem);
    const int tid = threadIdx.x;
    const int hg  = blockIdx.x;
    const int rb  = blockIdx.y;
    const int wid = tid >> 5;
    const int lane = tid & 31;
    const int m0  = (wid >> 1) * 16;
    const int n0w = (wid & 1) * 8;

    for (int f = tid; f < 64 * 256; f += THREADS) {
        const int n = f >> 8, k = f & 255;
        const int G = (n >> 4) * HID + hg * 16 + (n & 15);
        const float wv = Wih[G * EMB + k];
        const __nv_bfloat16 wh = __float2bfloat16(wv);
        const __nv_bfloat16 wl = __float2bfloat16(wv - __bfloat162float(wh));
        const int off = n * 512 + (((k >> 3) ^ (n & 7)) << 4) + (k & 7) * 2;
        *(__nv_bfloat16*)(smem + P_BHI + off) = wh;
        *(__nv_bfloat16*)(smem + P_BLO + off) = wl;
    }
    int* toks = (int*)(smem + P_TOK);

    float biasr[4][2];
#pragma unroll
    for (int ni = 0; ni < 4; ni++)
#pragma unroll
        for (int b = 0; b < 2; b++) {
            const int G = ni * HID + hg * 16 + n0w + 2 * (lane & 3) + b;
            biasr[ni][b] = bih[G] + bhh[G];
        }

    const uint32_t a_off = (uint32_t)((lane >> 4) * 2048 + (m0 + (lane & 15)) * 16);
    const int nl0 = n0w + ((lane >> 4) << 4) + (lane & 7);
    const uint32_t bHi0 = sb + P_BHI + (uint32_t)(nl0 * 512);
    const uint32_t bHi1 = sb + P_BHI + (uint32_t)((nl0 + 32) * 512);
    const uint32_t bLo0 = bHi0 + 32768;
    const uint32_t bLo1 = bHi1 + 32768;
    const uint32_t nx7  = (uint32_t)(lane & 7);
    const uint32_t kbit = (uint32_t)((lane >> 3) & 1);

    const int srow0 = tid >> 3, srow1 = 64 + (tid >> 3), scell = tid & 7;
    const uint32_t sd0 = (uint32_t)(scell * 2048 + srow0 * 16);
    const uint32_t sd1 = (uint32_t)(scell * 2048 + srow1 * 16);

    __syncthreads();

#pragma unroll 1
    for (int st = 0; st < 16; st++) {
        const int t = rb * 4 + (st >> 2);
        const int bgi = st & 3;
        const int nblk = bgi * 128;
        if (tid < 128) {
            const int n = nblk + tid;
            toks[tid] = (n < NBATCH) ? in1[(size_t)n * T + t]
                                     : in2[(size_t)(n - NBATCH) * T + t];
        }
        __syncthreads();

        auto stage = [&](int c) {
            const uint32_t buf = sb + P_A + (uint32_t)((c & 1) * 32768);
            const int kk = c * 64 + scell * 8;
            cp16_ca(buf + sd0,         g_ehi + (size_t)toks[srow0] * EMB + kk);
            cp16_ca(buf + sd1,         g_ehi + (size_t)toks[srow1] * EMB + kk);
            cp16_ca(buf + 16384 + sd0, g_elo + (size_t)toks[srow0] * EMB + kk);
            cp16_ca(buf + 16384 + sd1, g_elo + (size_t)toks[srow1] * EMB + kk);
            asm volatile("cp.async.commit_group;");
        };
        stage(0);
        stage(1);

        float acc[4][4];
#pragma unroll
        for (int ni = 0; ni < 4; ni++)
#pragma unroll
            for (int e = 0; e < 4; e++) acc[ni][e] = biasr[ni][e & 1];

#pragma unroll 1
        for (int c = 0; c < 4; c++) {
            if (c < 3) { asm volatile("cp.async.wait_group 1;"); }
            else       { asm volatile("cp.async.wait_group 0;"); }
            __syncthreads();
            chunk_compute(sb + P_A + (uint32_t)((c & 1) * 32768), a_off,
                          bHi0, bHi1, bLo0, bLo1, nx7, kbit, c * 8, acc);
            __syncthreads();
            if (c + 2 < 4) stage(c + 2);
        }

        // store XG tile in fragment-native layout (fully coalesced); t-stride 2^20
        {
            float* tbl = (t < 256) ? g_xgA : g_xgB;
            const size_t base =
                (((size_t)(t & 255) << 20)) +
                (((size_t)(hg * 4 + bgi)) << 13) + (size_t)tid * 16;
#pragma unroll
            for (int ni = 0; ni < 4; ni++)
                *(float4*)(tbl + base + ni * 4) =
                    make_float4(acc[ni][0], acc[ni][1], acc[ni][2], acc[ni][3]);
        }
        __syncthreads();
    }
}

// ---------------- persistent recurrent kernel (K=512) ----------------
__global__ void __launch_bounds__(THREADS, 1)
lstm_rec_kernel(const float* __restrict__ Whh,
                const float* __restrict__ Wfc, const float* __restrict__ bfc,
                float* __restrict__ out)
{
    extern __shared__ char smem[];
    const uint32_t sb = smem_u32(smem);
    const int tid = threadIdx.x;
    const int bid = blockIdx.x;
    const int hg  = bid & 31;
    const int bg  = bid >> 5;
    const int nbase = bg * 128;
    const int wid = tid >> 5;
    const int lane = tid & 31;
    const int m0  = (wid >> 1) * 16;
    const int n0w = (wid & 1) * 8;

    for (int f = tid; f < 64 * 512; f += THREADS) {
        const int n = f >> 9, k = f & 511;
        const int G = (n >> 4) * HID + hg * 16 + (n & 15);
        const float wv = Whh[G * HID + k];
        const __nv_bfloat16 wh = __float2bfloat16(wv);
        const __nv_bfloat16 wl = __float2bfloat16(wv - __bfloat162float(wh));
        const int off = n * 1024 + (((k >> 3) ^ (n & 7)) << 4) + (k & 7) * 2;
        *(__nv_bfloat16*)(smem + R_BHI + off) = wh;
        *(__nv_bfloat16*)(smem + R_BLO + off) = wl;
    }

    const uint32_t a_off = (uint32_t)((lane >> 4) * 2048 + (m0 + (lane & 15)) * 16);
    const int nl0 = n0w + ((lane >> 4) << 4) + (lane & 7);
    const uint32_t bHi0 = sb + R_BHI + (uint32_t)(nl0 * 1024);
    const uint32_t bHi1 = sb + R_BHI + (uint32_t)((nl0 + 32) * 1024);
    const uint32_t bLo0 = bHi0 + 65536;
    const uint32_t bLo1 = bHi1 + 65536;
    const uint32_t nx7  = (uint32_t)(lane & 7);
    const uint32_t kbit = (uint32_t)((lane >> 3) & 1);

    const int srow0 = tid >> 3, srow1 = 64 + (tid >> 3), scell = tid & 7;
    const uint32_t sd0 = (uint32_t)(scell * 2048 + srow0 * 16);
    const uint32_t sd1 = (uint32_t)(scell * 2048 + srow1 * 16);
    const size_t hoff0 = (size_t)(nbase + srow0) * HID + scell * 8;
    const size_t hoff1 = (size_t)(nbase + srow1) * HID + scell * 8;

    const int rA = m0 + (lane >> 2);
    const int jc = n0w + 2 * (lane & 3);
    const size_t xg_toff = ((size_t)(hg * 4 + bg) << 13) + (size_t)tid * 16;

    float cst[4];
#pragma unroll
    for (int i = 0; i < 4; i++) cst[i] = 0.0f;

    grid_sync();   // prep + xg done (stream order), B built everywhere

#pragma unroll 1
    for (int t = 0; t < T; t++) {
        const int hb = t & 1;
        const __nv_bfloat16* hh = g_hhi[hb];
        const __nv_bfloat16* hl = g_hlo[hb];

        auto stage = [&](int c) {
            const uint32_t buf = sb + R_A + (uint32_t)((c & 1) * 32768);
            const int kk = c * 64;
            cp16_cg(buf + sd0,         hh + hoff0 + kk);
            cp16_cg(buf + sd1,         hh + hoff1 + kk);
            cp16_cg(buf + 16384 + sd0, hl + hoff0 + kk);
            cp16_cg(buf + 16384 + sd1, hl + hoff1 + kk);
            asm volatile("cp.async.commit_group;");
        };
        stage(0);
        stage(1);

        // acc init from XG tile (4 coalesced LDG.128, overlap with staging); t-stride 2^20
        float acc[4][4];
        {
            const float* tbl = (t < 256) ? g_xgA : g_xgB;
            const size_t base = (((size_t)(t & 255)) << 20) + xg_toff;
#pragma unroll
            for (int ni = 0; ni < 4; ni++) {
                float4 v = __ldcg((const float4*)(tbl + base + ni * 4));
                acc[ni][0] = v.x; acc[ni][1] = v.y; acc[ni][2] = v.z; acc[ni][3] = v.w;
            }
        }

#pragma unroll 1
        for (int c = 0; c < 8; c++) {
            if (c < 7) { asm volatile("cp.async.wait_group 1;"); }
            else       { asm volatile("cp.async.wait_group 0;"); }
            __syncthreads();
            chunk_compute(sb + R_A + (uint32_t)((c & 1) * 32768), a_off,
                          bHi0, bHi1, bLo0, bLo1, nx7, kbit, c * 8, acc);
            __syncthreads();
            if (c + 2 < 8) stage(c + 2);
        }

        // pointwise LSTM (gates in-register)
        __nv_bfloat16* whh_ = g_hhi[hb ^ 1];
        __nv_bfloat16* whl_ = g_hlo[hb ^ 1];
        uint32_t packh[2], packl[2];
#pragma unroll
        for (int e = 0; e < 4; e++) {
            float ig = sigf(acc[0][e]);
            float fg = sigf(acc[1][e]);
            float gg = tanhx(acc[2][e]);
            float og = sigf(acc[3][e]);
            cst[e] = fg * cst[e] + ig * gg;
            float hv = og * tanhx(cst[e]);
            __nv_bfloat16 hb16 = __float2bfloat16(hv);
            __nv_bfloat16 lb16 = __float2bfloat16(hv - __bfloat162float(hb16));
            const int half = e >> 1, pos = (e & 1) * 16;
            if (pos == 0) { packh[half] = *(unsigned short*)&hb16;
                            packl[half] = *(unsigned short*)&lb16; }
            else { packh[half] |= (uint32_t)(*(unsigned short*)&hb16) << 16;
                   packl[half] |= (uint32_t)(*(unsigned short*)&lb16) << 16; }
        }
        {
            const size_t o0 = (size_t)(nbase + rA) * HID + hg * 16 + jc;
            const size_t o1 = (size_t)(nbase + rA + 8) * HID + hg * 16 + jc;
            *(uint32_t*)(whh_ + o0) = packh[0];
            *(uint32_t*)(whl_ + o0) = packl[0];
            *(uint32_t*)(whh_ + o1) = packh[1];
            *(uint32_t*)(whl_ + o1) = packl[1];
        }

        grid_sync();
    }

    // final: h = h1*h2 -> FC(2) -> softmax
    if (bid == 0 && tid < NBATCH) {
        const int n = tid;
        const __nv_bfloat16* a_h = g_hhi[0] + (size_t)n * HID;
        const __nv_bfloat16* a_l = g_hlo[0] + (size_t)n * HID;
        const __nv_bfloat16* b_h = g_hhi[0] + (size_t)(n + NBATCH) * HID;
        const __nv_bfloat16* b_l = g_hlo[0] + (size_t)(n + NBATCH) * HID;
        float l0 = bfc[0], l1 = bfc[1];
#pragma unroll 4
        for (int j = 0; j < HID; j++) {
            float h1 = __bfloat162float(a_h[j]) + __bfloat162float(a_l[j]);
            float h2 = __bfloat162float(b_h[j]) + __bfloat162float(b_l[j]);
            float hp = h1 * h2;
            l0 = __fmaf_rn(hp, Wfc[j], l0);
            l1 = __fmaf_rn(hp, Wfc[HID + j], l1);
        }
        float m  = fmaxf(l0, l1);
        float e0 = __expf(l0 - m);
        float e1 = __expf(l1 - m);
        float s  = __fdividef(1.0f, e0 + e1);
        out[n * 2 + 0] = e0 * s;
        out[n * 2 + 1] = e1 * s;
    }
}

extern "C" void kernel_launch(void* const* d_in, const int* in_sizes, int n_in,
                              void* d_out, int out_size)
{
    (void)in_sizes; (void)n_in; (void)out_size;
    const int*   in1 = (const int*)d_in[0];
    const int*   in2 = (const int*)d_in[1];
    const float* emb = (const float*)d_in[2];
    const float* Wih = (const float*)d_in[3];
    const float* Whh = (const float*)d_in[4];
    const float* bih = (const float*)d_in[5];
    const float* bhh = (const float*)d_in[6];
    const float* Wfc = (const float*)d_in[7];
    const float* bfc = (const float*)d_in[8];
    float* out = (float*)d_out;

    prep_kernel<<<2048, 256>>>(emb);

    cudaFuncSetAttribute(xg_kernel,
                         cudaFuncAttributeMaxDynamicSharedMemorySize, P_SMEM);
    dim3 g(32, 128);
    xg_kernel<<<g, THREADS, P_SMEM>>>(in1, in2, Wih, bih, bhh);

    cudaFuncSetAttribute(lstm_rec_kernel,
                         cudaFuncAttributeMaxDynamicSharedMemorySize, R_SMEM);
    lstm_rec_kernel<<<NBLOCKS, THREADS, R_SMEM>>>(Whh, Wfc, bfc, out);
}

// round 15
// speedup vs baseline: 1.1429x; 1.1429x over previous
#include <cuda_runtime.h>
#include <cuda_bf16.h>
#include <cstdint>
#include <cstddef>

#define VOCAB   50000
#define EMB     256
#define HID     512
#define NBATCH  256
#define T       512
#define NB      512
#define NBLOCKS 128
#define THREADS 512

// ---- recurrent kernel SMEM ----
#define R_BHI   0           // 64 rows x 1024 B (Whh hi, swizzled)      64 KB
#define R_BLO   65536       // 64 KB
#define R_A     131072      // 8 pairs x 3 bufs x 4 KB (pair-private)   96 KB
#define R_SMEM  229376

// ---- phase A kernel SMEM ----
#define P_BHI   0           // 64 rows x 512 B (Wih hi)                 32 KB
#define P_BLO   32768
#define P_A     65536       // 2 bufs x 32 KB
#define P_TOK   131072      // 128 ints
#define P_SMEM  131584

__device__ __nv_bfloat16 g_ehi[(size_t)VOCAB * EMB];
__device__ __nv_bfloat16 g_elo[(size_t)VOCAB * EMB];
__device__ __nv_bfloat16 g_hhi[2][NB * HID];
__device__ __nv_bfloat16 g_hlo[2][NB * HID];
// XG fragment-native tiles: tile id = ((t%256)*32 + hg)*4 + bg, 8192 floats, t-stride 2^20
__device__ float g_xgA[268435456];
__device__ float g_xgB[268435456];
__device__ unsigned g_cnt, g_gen;

// ---------------- helpers ----------------
__device__ __forceinline__ uint32_t smem_u32(const void* p) {
    uint32_t a;
    asm("{ .reg .u64 t; cvta.to.shared.u64 t, %1; cvt.u32.u64 %0, t; }" : "=r"(a) : "l"(p));
    return a;
}
__device__ __forceinline__ void cp16_ca(uint32_t d, const void* s) {
    asm volatile("cp.async.ca.shared.global [%0], [%1], 16;" :: "r"(d), "l"(s));
}
__device__ __forceinline__ void cp16_cg(uint32_t d, const void* s) {
    asm volatile("cp.async.cg.shared.global [%0], [%1], 16;" :: "r"(d), "l"(s));
}
__device__ __forceinline__ void ldsm4(uint32_t& r0, uint32_t& r1, uint32_t& r2, uint32_t& r3,
                                      uint32_t addr) {
    asm volatile("ldmatrix.sync.aligned.m8n8.x4.shared.b16 {%0,%1,%2,%3}, [%4];"
                 : "=r"(r0), "=r"(r1), "=r"(r2), "=r"(r3) : "r"(addr));
}
__device__ __forceinline__ void mma16816(float* c, const uint32_t* a, const uint32_t* b) {
    asm volatile(
        "mma.sync.aligned.m16n8k16.row.col.f32.bf16.bf16.f32 "
        "{%0,%1,%2,%3},{%4,%5,%6,%7},{%8,%9},{%0,%1,%2,%3};"
        : "+f"(c[0]), "+f"(c[1]), "+f"(c[2]), "+f"(c[3])
        : "r"(a[0]), "r"(a[1]), "r"(a[2]), "r"(a[3]), "r"(b[0]), "r"(b[1]));
}
__device__ __forceinline__ float sigf(float x) {
    return __fdividef(1.0f, 1.0f + __expf(-x));
}
__device__ __forceinline__ float tanhx(float x) {
    return __fmaf_rn(2.0f, sigf(2.0f * x), -1.0f);
}
__device__ __forceinline__ void grid_sync() {
    __syncthreads();
    if (threadIdx.x == 0) {
        volatile unsigned* genp = &g_gen;
        unsigned g = *genp;
        __threadfence();
        if (atomicAdd(&g_cnt, 1u) == NBLOCKS - 1) {
            g_cnt = 0;
            __threadfence();
            *genp = g + 1;
        } else {
            while (*genp == g) { }
        }
    }
    __syncthreads();
}

// Block-wide k64-chunk MMA (used by xg_kernel only)
__device__ __forceinline__ void chunk_compute(
    uint32_t aBuf, uint32_t a_off,
    uint32_t bHi0, uint32_t bHi1, uint32_t bLo0, uint32_t bLo1,
    uint32_t nx7, uint32_t kbit, int kc0, float acc[4][4])
{
#pragma unroll
    for (int s = 0; s < 4; s++) {
        uint32_t ah[4], al[4];
        ldsm4(ah[0], ah[1], ah[2], ah[3], aBuf + s * 4096 + a_off);
        ldsm4(al[0], al[1], al[2], al[3], aBuf + 16384 + s * 4096 + a_off);
        const uint32_t kc = (uint32_t)(kc0 + s * 2) + kbit;
        const uint32_t o = ((kc ^ nx7) << 4);
        uint32_t bh[4][2], bl[4][2];
        ldsm4(bh[0][0], bh[0][1], bh[1][0], bh[1][1], bHi0 + o);
        ldsm4(bh[2][0], bh[2][1], bh[3][0], bh[3][1], bHi1 + o);
        ldsm4(bl[0][0], bl[0][1], bl[1][0], bl[1][1], bLo0 + o);
        ldsm4(bl[2][0], bl[2][1], bl[3][0], bl[3][1], bLo1 + o);
#pragma unroll
        for (int ni = 0; ni < 4; ni++) {
            mma16816(acc[ni], ah, bh[ni]);
            mma16816(acc[ni], ah, bl[ni]);
            mma16816(acc[ni], al, bh[ni]);
        }
    }
}

// ---------------- prep ----------------
__global__ void prep_kernel(const float* __restrict__ emb) {
    const size_t stride = (size_t)gridDim.x * blockDim.x;
    size_t i = (size_t)blockIdx.x * blockDim.x + threadIdx.x;
    const size_t total = (size_t)VOCAB * EMB;
    for (size_t p = i; p < total; p += stride) {
        float v = emb[p];
        __nv_bfloat16 h = __float2bfloat16(v);
        g_ehi[p] = h;
        g_elo[p] = __float2bfloat16(v - __bfloat162float(h));
    }
    const __nv_bfloat16 z = __float2bfloat16(0.0f);
    for (size_t p = i; p < (size_t)NB * HID; p += stride) {
        g_hhi[0][p] = z;
        g_hlo[0][p] = z;
    }
}

// ---------------- Phase A: XG tiles = Wih . emb(tok) + bias ----------------
__global__ void __launch_bounds__(THREADS, 1)
xg_kernel(const int* __restrict__ in1, const int* __restrict__ in2,
          const float* __restrict__ Wih,
          const float* __restrict__ bih, const float* __restrict__ bhh)
{
    extern __shared__ char smem[];
    const uint32_t sb = smem_u32(smem);
    const int tid = threadIdx.x;
    const int hg  = blockIdx.x;
    const int rb  = blockIdx.y;
    const int wid = tid >> 5;
    const int lane = tid & 31;
    const int m0  = (wid >> 1) * 16;
    const int n0w = (wid & 1) * 8;

    for (int f = tid; f < 64 * 256; f += THREADS) {
        const int n = f >> 8, k = f & 255;
        const int G = (n >> 4) * HID + hg * 16 + (n & 15);
        const float wv = Wih[G * EMB + k];
        const __nv_bfloat16 wh = __float2bfloat16(wv);
        const __nv_bfloat16 wl = __float2bfloat16(wv - __bfloat162float(wh));
        const int off = n * 512 + (((k >> 3) ^ (n & 7)) << 4) + (k & 7) * 2;
        *(__nv_bfloat16*)(smem + P_BHI + off) = wh;
        *(__nv_bfloat16*)(smem + P_BLO + off) = wl;
    }
    int* toks = (int*)(smem + P_TOK);

    float biasr[4][2];
#pragma unroll
    for (int ni = 0; ni < 4; ni++)
#pragma unroll
        for (int b = 0; b < 2; b++) {
            const int G = ni * HID + hg * 16 + n0w + 2 * (lane & 3) + b;
            biasr[ni][b] = bih[G] + bhh[G];
        }

    const uint32_t a_off = (uint32_t)((lane >> 4) * 2048 + (m0 + (lane & 15)) * 16);
    const int nl0 = n0w + ((lane >> 4) << 4) + (lane & 7);
    const uint32_t bHi0 = sb + P_BHI + (uint32_t)(nl0 * 512);
    const uint32_t bHi1 = sb + P_BHI + (uint32_t)((nl0 + 32) * 512);
    const uint32_t bLo0 = bHi0 + 32768;
    const uint32_t bLo1 = bHi1 + 32768;
    const uint32_t nx7  = (uint32_t)(lane & 7);
    const uint32_t kbit = (uint32_t)((lane >> 3) & 1);

    const int srow0 = tid >> 3, srow1 = 64 + (tid >> 3), scell = tid & 7;
    const uint32_t sd0 = (uint32_t)(scell * 2048 + srow0 * 16);
    const uint32_t sd1 = (uint32_t)(scell * 2048 + srow1 * 16);

    __syncthreads();

#pragma unroll 1
    for (int st = 0; st < 16; st++) {
        const int t = rb * 4 + (st >> 2);
        const int bgi = st & 3;
        const int nblk = bgi * 128;
        if (tid < 128) {
            const int n = nblk + tid;
            toks[tid] = (n < NBATCH) ? in1[(size_t)n * T + t]
                                     : in2[(size_t)(n - NBATCH) * T + t];
        }
        __syncthreads();

        auto stage = [&](int c) {
            const uint32_t buf = sb + P_A + (uint32_t)((c & 1) * 32768);
            const int kk = c * 64 + scell * 8;
            cp16_ca(buf + sd0,         g_ehi + (size_t)toks[srow0] * EMB + kk);
            cp16_ca(buf + sd1,         g_ehi + (size_t)toks[srow1] * EMB + kk);
            cp16_ca(buf + 16384 + sd0, g_elo + (size_t)toks[srow0] * EMB + kk);
            cp16_ca(buf + 16384 + sd1, g_elo + (size_t)toks[srow1] * EMB + kk);
            asm volatile("cp.async.commit_group;");
        };
        stage(0);
        stage(1);

        float acc[4][4];
#pragma unroll
        for (int ni = 0; ni < 4; ni++)
#pragma unroll
            for (int e = 0; e < 4; e++) acc[ni][e] = biasr[ni][e & 1];

#pragma unroll 1
        for (int c = 0; c < 4; c++) {
            if (c < 3) { asm volatile("cp.async.wait_group 1;"); }
            else       { asm volatile("cp.async.wait_group 0;"); }
            __syncthreads();
            chunk_compute(sb + P_A + (uint32_t)((c & 1) * 32768), a_off,
                          bHi0, bHi1, bLo0, bLo1, nx7, kbit, c * 8, acc);
            __syncthreads();
            if (c + 2 < 4) stage(c + 2);
        }

        // store XG tile, fragment-native, t-stride 2^20
        {
            float* tbl = (t < 256) ? g_xgA : g_xgB;
            const size_t base =
                (((size_t)(t & 255) << 20)) +
                (((size_t)(hg * 4 + bgi)) << 13) + (size_t)tid * 16;
#pragma unroll
            for (int ni = 0; ni < 4; ni++)
                *(float4*)(tbl + base + ni * 4) =
                    make_float4(acc[ni][0], acc[ni][1], acc[ni][2], acc[ni][3]);
        }
        __syncthreads();
    }
}

// ---------------- persistent recurrent kernel (K=512, pair-private pipeline) ----------------
__global__ void __launch_bounds__(THREADS, 1)
lstm_rec_kernel(const float* __restrict__ Whh,
                const float* __restrict__ Wfc, const float* __restrict__ bfc,
                float* __restrict__ out)
{
    extern __shared__ char smem[];
    const uint32_t sb = smem_u32(smem);
    const int tid = threadIdx.x;
    const int bid = blockIdx.x;
    const int hg  = bid & 31;
    const int bg  = bid >> 5;
    const int nbase = bg * 128;
    const int wid = tid >> 5;
    const int lane = tid & 31;
    const int pr  = wid >> 1;          // pair 0..7, owns A rows [16pr, 16pr+16)
    const int n0w = (wid & 1) * 8;

    // resident B = Whh slice hi/lo (swizzled)
    for (int f = tid; f < 64 * 512; f += THREADS) {
        const int n = f >> 9, k = f & 511;
        const int G = (n >> 4) * HID + hg * 16 + (n & 15);
        const float wv = Whh[G * HID + k];
        const __nv_bfloat16 wh = __float2bfloat16(wv);
        const __nv_bfloat16 wl = __float2bfloat16(wv - __bfloat162float(wh));
        const int off = n * 1024 + (((k >> 3) ^ (n & 7)) << 4) + (k & 7) * 2;
        *(__nv_bfloat16*)(smem + R_BHI + off) = wh;
        *(__nv_bfloat16*)(smem + R_BLO + off) = wl;
    }

    // B ldsm lane constants (unchanged)
    const int nl0 = n0w + ((lane >> 4) << 4) + (lane & 7);
    const uint32_t bHi0 = sb + R_BHI + (uint32_t)(nl0 * 1024);
    const uint32_t bHi1 = sb + R_BHI + (uint32_t)((nl0 + 32) * 1024);
    const uint32_t bLo0 = bHi0 + 65536;
    const uint32_t bLo1 = bHi1 + 65536;
    const uint32_t nx7  = (uint32_t)(lane & 7);
    const uint32_t kbit = (uint32_t)((lane >> 3) & 1);

    // pair-private A: base + 3 bufs x 4096 B; layout [kcell 0..7][row 0..15][16B], hi@0 lo@+2048
    const uint32_t pbase = sb + R_A + (uint32_t)(pr * 12288);
    const uint32_t a_offp = (uint32_t)((lane >> 4) * 256 + (lane & 15) * 16);

    // pair staging map: 64 threads, 4 cp16 each per k64 chunk
    const int wtid = tid & 63;
    const int prow = wtid >> 2;        // 0..15
    const int psp  = wtid & 3;         // k16 segment
    const uint32_t pd0 = (uint32_t)((2 * psp)     * 256 + prow * 16);
    const uint32_t pd1 = (uint32_t)((2 * psp + 1) * 256 + prow * 16);
    const size_t hrow = (size_t)(nbase + 16 * pr + prow) * HID + psp * 16;

    // pointwise / XG coords
    const int rA = pr * 16 + (lane >> 2);
    const int jc = n0w + 2 * (lane & 3);
    const size_t xg_toff = ((size_t)(hg * 4 + bg) << 13) + (size_t)tid * 16;
    const int barid = 1 + pr;

    float cst[4];
#pragma unroll
    for (int i = 0; i < 4; i++) cst[i] = 0.0f;

    grid_sync();   // prep + xg done (stream order), B built everywhere

#pragma unroll 1
    for (int t = 0; t < T; t++) {
        const int hb = t & 1;
        const __nv_bfloat16* hh = g_hhi[hb];
        const __nv_bfloat16* hl = g_hlo[hb];

        auto stage = [&](int c, int bsel) {
            const uint32_t buf = pbase + (uint32_t)(bsel * 4096);
            const size_t so = hrow + c * 64;
            cp16_cg(buf + pd0,        hh + so);
            cp16_cg(buf + pd1,        hh + so + 8);
            cp16_cg(buf + 2048 + pd0, hl + so);
            cp16_cg(buf + 2048 + pd1, hl + so + 8);
            asm volatile("cp.async.commit_group;");
        };
        stage(0, 0);
        stage(1, 1);

        // acc init from XG tile (4 coalesced LDG.128, overlap with staging)
        float acc[4][4];
        {
            const float* tbl = (t < 256) ? g_xgA : g_xgB;
            const size_t base = (((size_t)(t & 255)) << 20) + xg_toff;
#pragma unroll
            for (int ni = 0; ni < 4; ni++) {
                float4 v = __ldcg((const float4*)(tbl + base + ni * 4));
                acc[ni][0] = v.x; acc[ni][1] = v.y; acc[ni][2] = v.z; acc[ni][3] = v.w;
            }
        }

        // pair-private self-paced pipeline: NO block-wide syncs
        int bc = 0;   // buffer of chunk c
        int bs = 2;   // buffer for chunk c+2
#pragma unroll 1
        for (int c = 0; c < 8; c++) {
            if (c < 7) { asm volatile("cp.async.wait_group 1;"); }
            else       { asm volatile("cp.async.wait_group 0;"); }
            asm volatile("bar.sync %0, 64;" :: "r"(barid) : "memory");

            const uint32_t abuf = pbase + (uint32_t)(bc * 4096);
#pragma unroll
            for (int s = 0; s < 4; s++) {
                uint32_t ah[4], al[4];
                ldsm4(ah[0], ah[1], ah[2], ah[3], abuf + s * 512 + a_offp);
                ldsm4(al[0], al[1], al[2], al[3], abuf + 2048 + s * 512 + a_offp);
                const uint32_t kc = (uint32_t)(c * 8 + s * 2) + kbit;
                const uint32_t o = ((kc ^ nx7) << 4);
                uint32_t bh[4][2], bl[4][2];
                ldsm4(bh[0][0], bh[0][1], bh[1][0], bh[1][1], bHi0 + o);
                ldsm4(bh[2][0], bh[2][1], bh[3][0], bh[3][1], bHi1 + o);
                ldsm4(bl[0][0], bl[0][1], bl[1][0], bl[1][1], bLo0 + o);
                ldsm4(bl[2][0], bl[2][1], bl[3][0], bl[3][1], bLo1 + o);
#pragma unroll
                for (int ni = 0; ni < 4; ni++) {
                    mma16816(acc[ni], ah, bh[ni]);
                    mma16816(acc[ni], ah, bl[ni]);
                    mma16816(acc[ni], al, bh[ni]);
                }
            }

            if (c + 2 < 8) stage(c + 2, bs);
            bc = (bc == 2) ? 0 : bc + 1;
            bs = (bs == 2) ? 0 : bs + 1;
        }

        // pointwise LSTM (gates in-register)
        __nv_bfloat16* whh_ = g_hhi[hb ^ 1];
        __nv_bfloat16* whl_ = g_hlo[hb ^ 1];
        uint32_t packh[2], packl[2];
#pragma unroll
        for (int e = 0; e < 4; e++) {
            float ig = sigf(acc[0][e]);
            float fg = sigf(acc[1][e]);
            float gg = tanhx(acc[2][e]);
            float og = sigf(acc[3][e]);
            cst[e] = fg * cst[e] + ig * gg;
            float hv = og * tanhx(cst[e]);
            __nv_bfloat16 hb16 = __float2bfloat16(hv);
            __nv_bfloat16 lb16 = __float2bfloat16(hv - __bfloat162float(hb16));
            const int half = e >> 1, pos = (e & 1) * 16;
            if (pos == 0) { packh[half] = *(unsigned short*)&hb16;
                            packl[half] = *(unsigned short*)&lb16; }
            else { packh[half] |= (uint32_t)(*(unsigned short*)&hb16) << 16;
                   packl[half] |= (uint32_t)(*(unsigned short*)&lb16) << 16; }
        }
        {
            const size_t o0 = (size_t)(nbase + rA) * HID + hg * 16 + jc;
            const size_t o1 = (size_t)(nbase + rA + 8) * HID + hg * 16 + jc;
            *(uint32_t*)(whh_ + o0) = packh[0];
            *(uint32_t*)(whl_ + o0) = packl[0];
            *(uint32_t*)(whh_ + o1) = packh[1];
            *(uint32_t*)(whl_ + o1) = packl[1];
        }

        grid_sync();
    }

    // final: h = h1*h2 -> FC(2) -> softmax (final h in buf 0)
    if (bid == 0 && tid < NBATCH) {
        const int n = tid;
        const __nv_bfloat16* a_h = g_hhi[0] + (size_t)n * HID;
        const __nv_bfloat16* a_l = g_hlo[0] + (size_t)n * HID;
        const __nv_bfloat16* b_h = g_hhi[0] + (size_t)(n + NBATCH) * HID;
        const __nv_bfloat16* b_l = g_hlo[0] + (size_t)(n + NBATCH) * HID;
        float l0 = bfc[0], l1 = bfc[1];
#pragma unroll 4
        for (int j = 0; j < HID; j++) {
            float h1 = __bfloat162float(a_h[j]) + __bfloat162float(a_l[j]);
            float h2 = __bfloat162float(b_h[j]) + __bfloat162float(b_l[j]);
            float hp = h1 * h2;
            l0 = __fmaf_rn(hp, Wfc[j], l0);
            l1 = __fmaf_rn(hp, Wfc[HID + j], l1);
        }
        float m  = fmaxf(l0, l1);
        float e0 = __expf(l0 - m);
        float e1 = __expf(l1 - m);
        float s  = __fdividef(1.0f, e0 + e1);
        out[n * 2 + 0] = e0 * s;
        out[n * 2 + 1] = e1 * s;
    }
}

extern "C" void kernel_launch(void* const* d_in, const int* in_sizes, int n_in,
                              void* d_out, int out_size)
{
    (void)in_sizes; (void)n_in; (void)out_size;
    const int*   in1 = (const int*)d_in[0];
    const int*   in2 = (const int*)d_in[1];
    const float* emb = (const float*)d_in[2];
    const float* Wih = (const float*)d_in[3];
    const float* Whh = (const float*)d_in[4];
    const float* bih = (const float*)d_in[5];
    const float* bhh = (const float*)d_in[6];
    const float* Wfc = (const float*)d_in[7];
    const float* bfc = (const float*)d_in[8];
    float* out = (float*)d_out;

    prep_kernel<<<2048, 256>>>(emb);

    cudaFuncSetAttribute(xg_kernel,
                         cudaFuncAttributeMaxDynamicSharedMemorySize, P_SMEM);
    dim3 g(32, 128);
    xg_kernel<<<g, THREADS, P_SMEM>>>(in1, in2, Wih, bih, bhh);

    cudaFuncSetAttribute(lstm_rec_kernel,
                         cudaFuncAttributeMaxDynamicSharedMemorySize, R_SMEM);
    lstm_rec_kernel<<<NBLOCKS, THREADS, R_SMEM>>>(Whh, Wfc, bfc, out);
}